// round 6
// baseline (speedup 1.0000x reference)
#include <cuda_runtime.h>

// AvgSeq: out[b,s,d] = cumsum_s(x[b,s,d]) / (s+1)
// Single-pass decoupled-lookback scan. B=16, S=8192, D=256, fp32.

#define B 16
#define S 8192
#define D 256
#define CLEN 64
#define NC (S / CLEN)   // 128 chunks per batch

// Lookback state. agg/pref: per-(b,chunk) vectors of D floats.
__device__ float g_agg [B * NC * D];
__device__ float g_pref[B * NC * D];
__device__ int   g_flag[B * NC];     // 0=invalid, 1=aggregate ready, 2=prefix ready
__device__ float g_recip[S];         // 1/(s+1)

// Reset flags + fill reciprocal table. Runs every launch (graph-safe).
__global__ void init_state() {
    int i = blockIdx.x * blockDim.x + threadIdx.x;
    if (i < S) g_recip[i] = 1.0f / (float)(i + 1);
    if (i < B * NC) g_flag[i] = 0;
}

__global__ void __launch_bounds__(D) scan_kernel(const float* __restrict__ x,
                                                 float* __restrict__ y) {
    const int d = threadIdx.x;
    const int c = blockIdx.x;      // chunk within batch
    const int b = blockIdx.y;
    const int lane_base = (b * NC + c) * D + d;
    const size_t base = ((size_t)b * S + (size_t)c * CLEN) * D + d;
    const float* p = x + base;

    // Phase 1: load chunk into registers (64 independent loads -> max MLP),
    // compute aggregate.
    float v[CLEN];
#pragma unroll
    for (int s = 0; s < CLEN; ++s) v[s] = p[(size_t)s * D];

    float agg = 0.f;
#pragma unroll
    for (int s = 0; s < CLEN; ++s) agg += v[s];

    float excl = 0.f;

    if (c == 0) {
        // First chunk: inclusive prefix == aggregate. Publish flag=2 directly;
        // NEVER publish flag=1 (a successor catching flag=1 on chunk 0 would
        // walk past index 0).
        g_pref[lane_base] = agg;
        __threadfence();
        __syncthreads();
        if (d == 0) atomicExch(&g_flag[b * NC], 2);
    } else {
        // Publish aggregate (flag=1).
        g_agg[lane_base] = agg;
        __threadfence();
        __syncthreads();
        if (d == 0) atomicExch(&g_flag[b * NC + c], 1);

        // Phase 2: decoupled lookback to get exclusive prefix.
        __shared__ int s_state;
        int pidx = c - 1;
        while (pidx >= 0) {
            if (d == 0) {
                int f;
                do { f = atomicAdd(&g_flag[b * NC + pidx], 0); } while (f == 0);
                __threadfence();
                s_state = f;
            }
            __syncthreads();
            const int f = s_state;
            const float* src = (f == 2 ? g_pref : g_agg) + (b * NC + pidx) * D + d;
            excl += __ldcg(src);
            __syncthreads();   // protect s_state before next iteration
            if (f == 2) break;
            --pidx;
        }

        // Publish inclusive prefix (flag=2).
        g_pref[lane_base] = excl + agg;
        __threadfence();
        __syncthreads();
        if (d == 0) atomicExch(&g_flag[b * NC + c], 2);
    }

    // Phase 3: emit output from registers. recip loads are warp-uniform
    // broadcasts (L1-hot).
    float run = excl;
    float* q = y + base;
    const float* r = g_recip + c * CLEN;
#pragma unroll
    for (int s = 0; s < CLEN; ++s) {
        run += v[s];
        q[(size_t)s * D] = run * r[s];
    }
}

extern "C" void kernel_launch(void* const* d_in, const int* in_sizes, int n_in,
                              void* d_out, int out_size) {
    const float* x = (const float*)d_in[0];
    float* y = (float*)d_out;

    init_state<<<(S + 255) / 256, 256>>>();
    dim3 grid(NC, B);
    scan_kernel<<<grid, D>>>(x, y);
}

// round 10
// speedup vs baseline: 2.0598x; 2.0598x over previous
#include <cuda_runtime.h>

// AvgSeq: out[b,s,d] = cumsum_s(x[b,s,d]) / (s+1)
// 3-pass chunked scan. B=16, S=8192, D=256, fp32.
// Pass1 runs chunks in REVERSE so the low addresses are L2-fresh when pass3
// (forward order) re-reads them. Output stores are evict-first (__stcs) to
// keep the input resident in L2.

#define B 16
#define S 8192
#define D 256
#define NC 64            // seq chunks
#define CLEN (S / NC)    // 128 seq steps per chunk

// Per-(b, chunk, d) partial sums: 16*64*256 floats = 1 MB.
__device__ float g_partial[B * NC * D];

// Pass 1: thread d sums its chunk. Reverse chunk mapping for L2 retention.
__global__ void __launch_bounds__(D) pass1_chunk_sums(const float* __restrict__ x) {
    const int d = threadIdx.x;
    const int c = (NC - 1) - blockIdx.x;   // reverse order
    const int b = blockIdx.y;
    const float* p = x + ((size_t)b * S + (size_t)c * CLEN) * D + d;
    float sum = 0.f;
#pragma unroll 16
    for (int s = 0; s < CLEN; ++s) {
        sum += p[(size_t)s * D];
    }
    g_partial[(b * NC + c) * D + d] = sum;
}

// Pass 2: exclusive scan over the NC chunk sums per (b, d) lane.
// Fully unrolled: 64 independent loads batch up (high MLP), then reg scan.
__global__ void __launch_bounds__(D) pass2_scan_sums() {
    const int d = threadIdx.x;
    const int b = blockIdx.x;
    float v[NC];
#pragma unroll
    for (int c = 0; c < NC; ++c) v[c] = g_partial[(b * NC + c) * D + d];
    float run = 0.f;
#pragma unroll
    for (int c = 0; c < NC; ++c) {
        const float t = v[c];
        g_partial[(b * NC + c) * D + d] = run;   // exclusive prefix
        run += t;
    }
}

// Pass 3: re-read input (hopefully L2-hot), local scan + offset, scale by
// per-block shared-memory reciprocal table, evict-first stores.
__global__ void __launch_bounds__(D) pass3_scan_out(const float* __restrict__ x,
                                                    float* __restrict__ y) {
    __shared__ float s_recip[CLEN];
    const int d = threadIdx.x;
    const int c = blockIdx.x;
    const int b = blockIdx.y;
    const int s0 = c * CLEN;

    if (threadIdx.x < CLEN)
        s_recip[threadIdx.x] = __fdividef(1.0f, (float)(s0 + threadIdx.x + 1));
    __syncthreads();

    float run = g_partial[(b * NC + c) * D + d];
    const size_t base = ((size_t)b * S + (size_t)c * CLEN) * D + d;
    const float* p = x + base;
    float* q = y + base;
#pragma unroll 8
    for (int s = 0; s < CLEN; ++s) {
        run += p[(size_t)s * D];
        __stcs(q + (size_t)s * D, run * s_recip[s]);
    }
}

extern "C" void kernel_launch(void* const* d_in, const int* in_sizes, int n_in,
                              void* d_out, int out_size) {
    const float* x = (const float*)d_in[0];
    float* y = (float*)d_out;

    dim3 grid(NC, B);
    pass1_chunk_sums<<<grid, D>>>(x);
    pass2_scan_sums<<<B, D>>>();
    pass3_scan_out<<<grid, D>>>(x, y);
}